// round 6
// baseline (speedup 1.0000x reference)
#include <cuda_runtime.h>

typedef unsigned long long ull;

// ---- Interleaved weight tables ----
// Each tap stored as float4 (cos, sin, sin, cos):
//   lo half W  = (wc, ws):  ffma2(S, A, W)  -> (c*wc, s*ws),  Sx = lo+hi
//   hi half Wr = (ws, wc):  ffma2(T, A, Wr) -> (c*ws, s*wc),  Sy = hi-lo
__device__ __align__(16) float4 g_w1q[16];     // [co*4 + i*2 + j]
__device__ __align__(16) float4 g_w2q[520];    // [co*65 + c*16 + i*4 + j]
__device__ __align__(16) float4 g_wfq[2880];   // [o*288 + f]

__global__ void prep_kernel(const float* __restrict__ w1,
                            const float* __restrict__ w2,
                            const float* __restrict__ wf) {
    int t = threadIdx.x;
    if (t < 16) {
        float s, c; sincosf(w1[t], &s, &c);
        g_w1q[t] = make_float4(c, s, s, c);
    }
    for (int i = t; i < 512; i += blockDim.x) {
        int co = i >> 6, r = i & 63;
        float s, c; sincosf(w2[i], &s, &c);
        g_w2q[co * 65 + r] = make_float4(c, s, s, c);
    }
    for (int i = t; i < 2880; i += blockDim.x) {
        int f = i / 10, o = i % 10;
        float s, c; sincosf(wf[i], &s, &c);
        g_wfq[o * 288 + f] = make_float4(c, s, s, c);
    }
}

// packed dual-FMA: acc(lo,hi) += a(lo,hi) * b(lo,hi)
static __device__ __forceinline__ void ffma2(ull& acc, ull a, ull b) {
    asm("fma.rn.f32x2 %0, %1, %2, %0;" : "+l"(acc) : "l"(a), "l"(b));
}
static __device__ __forceinline__ float f2lo(ull v) { return __uint_as_float((unsigned)v); }
static __device__ __forceinline__ float f2hi(ull v) { return __uint_as_float((unsigned)(v >> 32)); }

// MUFU-free sincos: quadrant reduction + minimax polys (FMA/ALU pipes only)
static __device__ __forceinline__ void fast_sincos(float x, float& s, float& c) {
    float t = fmaf(x, 0.63661977236758134f, 12582912.0f);
    unsigned q = __float_as_uint(t);
    float kf = t - 12582912.0f;
    float r = fmaf(kf, -1.57079625129699707031f, x);
    r = fmaf(kf, -7.54978941586159e-08f, r);
    float y = r * r;
    float ps = fmaf(y, -1.95152959e-4f, 8.33216087e-3f);
    ps = fmaf(y, ps, -1.66666546e-1f);
    float s0 = fmaf(r * y, ps, r);
    float pc = fmaf(y, 2.44331571e-5f, -1.38873162e-3f);
    pc = fmaf(y, pc, 4.16666232e-2f);
    pc = fmaf(y, pc, -0.5f);
    float c0 = fmaf(y, pc, 1.0f);
    bool sw = q & 1u;
    float ss = sw ? c0 : s0;
    float cc = sw ? s0 : c0;
    unsigned sgs = (q & 2u) << 30;
    unsigned sgc = ((q + 1u) & 2u) << 30;
    s = __uint_as_float(__float_as_uint(ss) ^ sgs);
    c = __uint_as_float(__float_as_uint(cc) ^ sgc);
}

// MUFU-free rsqrt: bit trick + 2 Newton iterations
static __device__ __forceinline__ float fast_rsqrt(float d) {
    float y = __uint_as_float(0x5F3759DFu - (__float_as_uint(d) >> 1));
    float h = 0.5f * d;
    y = y * fmaf(-(h * y), y, 1.5f);
    y = y * fmaf(-(h * y), y, 1.5f);
    return y;
}

__global__ __launch_bounds__(320, 4) void ring_kernel(const float* __restrict__ x,
                                                      float* __restrict__ out) {
    __shared__ __align__(16) float2 s_px[784];   // pixel (c,s), 28x28
    __shared__ __align__(16) float2 s_h1[784];   // conv1 out [co*196 + y*14 + x]
    __shared__ __align__(16) float2 s_h2[288];   // conv2 out [(ho*6+wo)*8 + co]
    __shared__ __align__(16) float4 s_w1[16];
    __shared__ __align__(16) float4 s_w2[520];

    const int tid = threadIdx.x;

    // ---- Stage 0: pixel trig -> interleaved (c,s); STS.128 pairs ----
    const float4* xb4 = reinterpret_cast<const float4*>(x + blockIdx.x * 784);
    float4* px4 = reinterpret_cast<float4*>(s_px);
    for (int i = tid; i < 196; i += 320) {
        float4 v = xb4[i];
        float s0, c0, s1, c1, s2, c2, s3, c3;
        fast_sincos(v.x, s0, c0);
        fast_sincos(v.y, s1, c1);
        fast_sincos(v.z, s2, c2);
        fast_sincos(v.w, s3, c3);
        px4[2 * i]     = make_float4(c0, s0, c1, s1);
        px4[2 * i + 1] = make_float4(c2, s2, c3, s3);
    }
    if (tid < 16) s_w1[tid] = g_w1q[tid];
    for (int i = tid; i < 520; i += 320) s_w2[i] = g_w2q[i];
    __syncthreads();

    // ---- Stage 1: conv1 2x2 s2 -> 14x14x4; one spatial pos/thread, 4 co ----
    if (tid < 196) {
        int py = tid / 14, px = tid % 14;
        int base = py * 56 + px * 2;
        ulonglong2 r0 = *(const ulonglong2*)&s_px[base];        // taps (0,0),(0,1)
        ulonglong2 r1 = *(const ulonglong2*)&s_px[base + 28];   // taps (1,0),(1,1)
        int dst = py * 14 + px;
#pragma unroll
        for (int co = 0; co < 4; co++) {
            const ulonglong2* w = (const ulonglong2*)&s_w1[co * 4];
            ulonglong2 w0 = w[0], w1 = w[1], w2 = w[2], w3 = w[3];
            ull S = 0, T = 0;
            ffma2(S, r0.x, w0.x); ffma2(T, r0.x, w0.y);
            ffma2(S, r0.y, w1.x); ffma2(T, r0.y, w1.y);
            ffma2(S, r1.x, w2.x); ffma2(T, r1.x, w2.y);
            ffma2(S, r1.y, w3.x); ffma2(T, r1.y, w3.y);
            float Sx = f2lo(S) + f2hi(S);
            float Sy = f2hi(T) - f2lo(T);
            float r = fast_rsqrt(fmaxf(Sx * Sx + Sy * Sy, 1e-30f));
            s_h1[co * 196 + dst] = make_float2(Sx * r, Sy * r);
        }
    }
    __syncthreads();

    // ---- Stage 2: conv2 4x4 s2, 4->8 ch -> 288 outputs; 2 outputs/thread ----
    int st = tid + ((blockIdx.x & 3) << 5);
    if (st >= 320) st -= 320;
    if (st < 144) {
        int co = st & 7, q = st >> 3;         // co fastest -> A broadcast in 8-lane groups
        int ho = q / 3, wp = q % 3;           // outputs wo = 2wp, 2wp+1
        const int vbase = ho * 28 + wp * 4;   // (2ho)*14 + wp*4
        const int wbase = co * 65;
        ull SA = 0, TA = 0, SB = 0, TB = 0;
#pragma unroll
        for (int c = 0; c < 4; c++) {
#pragma unroll
            for (int i = 0; i < 4; i++) {
                int vb = c * 196 + vbase + i * 14;
                ulonglong2 a01 = *(const ulonglong2*)&s_h1[vb];
                ulonglong2 a23 = *(const ulonglong2*)&s_h1[vb + 2];
                ulonglong2 a45 = *(const ulonglong2*)&s_h1[vb + 4];
                const ulonglong2* w = (const ulonglong2*)&s_w2[wbase + c * 16 + i * 4];
                ulonglong2 w0 = w[0], w1 = w[1];
                ffma2(SA, a01.x, w0.x); ffma2(TA, a01.x, w0.y);
                ffma2(SA, a01.y, w1.x); ffma2(TA, a01.y, w1.y);
                ffma2(SB, a23.x, w0.x); ffma2(TB, a23.x, w0.y);
                ffma2(SB, a23.y, w1.x); ffma2(TB, a23.y, w1.y);
                ulonglong2 w2_ = w[2], w3_ = w[3];
                ffma2(SA, a23.x, w2_.x); ffma2(TA, a23.x, w2_.y);
                ffma2(SA, a23.y, w3_.x); ffma2(TA, a23.y, w3_.y);
                ffma2(SB, a45.x, w2_.x); ffma2(TB, a45.x, w2_.y);
                ffma2(SB, a45.y, w3_.x); ffma2(TB, a45.y, w3_.y);
            }
        }
        int d0 = (ho * 6 + 2 * wp) * 8 + co;
        {
            float Sx = f2lo(SA) + f2hi(SA);
            float Sy = f2hi(TA) - f2lo(TA);
            float r = fast_rsqrt(fmaxf(Sx * Sx + Sy * Sy, 1e-30f));
            s_h2[d0] = make_float2(Sx * r, Sy * r);
        }
        {
            float Sx = f2lo(SB) + f2hi(SB);
            float Sy = f2hi(TB) - f2lo(TB);
            float r = fast_rsqrt(fmaxf(Sx * Sx + Sy * Sy, 1e-30f));
            s_h2[d0 + 8] = make_float2(Sx * r, Sy * r);
        }
    }
    __syncthreads();

    // ---- Stage 3: FF ring layer, one warp per class; wf from global ----
    int o = tid >> 5, lane = tid & 31;
    const ulonglong2* wfo = reinterpret_cast<const ulonglong2*>(g_wfq + o * 288);
    ull S = 0, T = 0;
    for (int f = lane; f < 288; f += 32) {
        ull a = *(const ull*)&s_h2[f];
        ulonglong2 w = __ldg(wfo + f);
        ffma2(S, a, w.x); ffma2(T, a, w.y);
    }
    float Sx = f2lo(S) + f2hi(S);
    float Sy = f2hi(T) - f2lo(T);
#pragma unroll
    for (int off = 16; off; off >>= 1) {
        Sx += __shfl_xor_sync(0xffffffff, Sx, off);
        Sy += __shfl_xor_sync(0xffffffff, Sy, off);
    }
    if (lane == 0)
        out[blockIdx.x * 10 + o] = Sy * fast_rsqrt(fmaxf(Sx * Sx + Sy * Sy, 1e-30f));
}

extern "C" void kernel_launch(void* const* d_in, const int* in_sizes, int n_in,
                              void* d_out, int out_size) {
    const float* x  = (const float*)d_in[0];
    const float* w1 = (const float*)d_in[1];
    const float* w2 = (const float*)d_in[2];
    const float* wf = (const float*)d_in[3];
    float* out = (float*)d_out;
    int B = in_sizes[0] / 784;
    prep_kernel<<<1, 512>>>(w1, w2, wf);
    ring_kernel<<<B, 320>>>(x, out);
}